// round 3
// baseline (speedup 1.0000x reference)
#include <cuda_runtime.h>
#include <math.h>
#include <stdint.h>

// Problem constants
#define Tt   512
#define Bb   64
#define Dd   256
#define Uu   512
#define Mm   64
#define NZt  2112   // 4*U + M

#define NUBLK 128   // u-blocks (4 u-cols each)
#define NEBLK 16    // e-blocks (4 e-cols each)
#define NBLK  144
#define NTHR  128

// ---------------- device scratch (static: no runtime allocation) ----------------
__device__ float g_Z[(size_t)Tt * NZt * Bb];        // Z[t][n][b] = x_t@Wcat + bcat  (~277MB)
__device__ float g_h2[2][Bb][Uu];                   // double-buffered hidden state
__device__ float g_cring[Mm][Bb][Uu];               // ring buffer of last 64 c vectors (8MB)
__device__ float g_ze[Bb][Mm];                      // pre-softmax e logits
__device__ unsigned int g_bar4[4];                  // striped grid barrier counters
__device__ unsigned int g_eflag;                    // e-ready counter

// ---------------- init: reset per-replay mutable state ----------------
__global__ void init_kernel() {
    int tid = blockIdx.x * blockDim.x + threadIdx.x;
    float* h0 = &g_h2[0][0][0];
    for (int i = tid; i < Bb * Uu; i += gridDim.x * blockDim.x) h0[i] = 0.0f;
    if (tid < 4) g_bar4[tid] = 0u;
    if (tid == 4) g_eflag = 0u;
}

// ---------------- precompute: Z[t][n][b] = bcat[n] + sum_k x[b][t][k]*Wcat[k][n] ----------------
// grid: (33 n-tiles of 64, 512 t), 256 threads, 64b x 64n tile, K=256 in 4 chunks.
__global__ __launch_bounds__(256) void precompute_kernel(
    const float* __restrict__ x,
    const float* __restrict__ Wi, const float* __restrict__ Wf,
    const float* __restrict__ Wo, const float* __restrict__ Wc,
    const float* __restrict__ We,
    const float* __restrict__ bi, const float* __restrict__ bf,
    const float* __restrict__ bo, const float* __restrict__ bc,
    const float* __restrict__ be)
{
    __shared__ float xs[64 * 65];   // x[b][k] chunk, padded
    __shared__ float Ws[64 * 64];   // W[k][n] chunk

    const int nt  = blockIdx.x;     // 0..32  (0..31: gates, 32: e)
    const int t   = blockIdx.y;
    const int tid = threadIdx.x;

    const float* W; const float* bv;
    switch (nt >> 3) {
        case 0:  W = Wi; bv = bi; break;
        case 1:  W = Wf; bv = bf; break;
        case 2:  W = Wo; bv = bo; break;
        case 3:  W = Wc; bv = bc; break;
        default: W = We; bv = be; break;
    }
    const int stride = (nt < 32) ? Uu : Mm;
    const int col0   = (nt & 7) * 64;   // nt==32 -> 0

    const int tx = tid & 15, ty = tid >> 4;

    float acc[4][4];
    #pragma unroll
    for (int j = 0; j < 4; j++) {
        float b0 = bv[col0 + tx * 4 + j];
        #pragma unroll
        for (int i = 0; i < 4; i++) acc[i][j] = b0;
    }

    for (int kb = 0; kb < 4; kb++) {
        __syncthreads();
        #pragma unroll
        for (int l = 0; l < 16; l++) {
            int idx = l * 256 + tid;
            int b = idx >> 6, kk = idx & 63;
            xs[b * 65 + kk] = x[(size_t)b * Tt * Dd + (size_t)t * Dd + kb * 64 + kk];
        }
        #pragma unroll
        for (int l = 0; l < 16; l++) {
            int idx = l * 256 + tid;
            int kk = idx >> 6, nn = idx & 63;
            Ws[kk * 64 + nn] = W[(size_t)(kb * 64 + kk) * stride + col0 + nn];
        }
        __syncthreads();
        #pragma unroll 16
        for (int kk = 0; kk < 64; kk++) {
            float4 wv = *reinterpret_cast<const float4*>(&Ws[kk * 64 + tx * 4]);
            #pragma unroll
            for (int i = 0; i < 4; i++) {
                float xv = xs[(ty * 4 + i) * 65 + kk];
                acc[i][0] += xv * wv.x;
                acc[i][1] += xv * wv.y;
                acc[i][2] += xv * wv.z;
                acc[i][3] += xv * wv.w;
            }
        }
    }

    #pragma unroll
    for (int j = 0; j < 4; j++) {
        int n = nt * 64 + tx * 4 + j;
        float4 v = make_float4(acc[0][j], acc[1][j], acc[2][j], acc[3][j]);
        *reinterpret_cast<float4*>(&g_Z[((size_t)t * NZt + n) * Bb + ty * 4]) = v;
    }
}

// ---------------- persistent recurrent kernel ----------------
// 144 blocks x 128 threads. Blocks 0..127: u-blocks (4 u cols -> 16 z cols).
// Blocks 128..143: e-blocks (4 e cols). One striped grid barrier per step.
__global__ __launch_bounds__(NTHR) void recur_kernel(
    float* __restrict__ out,
    const float* __restrict__ Ui, const float* __restrict__ Uf,
    const float* __restrict__ Uo, const float* __restrict__ Uc,
    const float* __restrict__ Ue)
{
    extern __shared__ float sm[];
    float* Us  = sm;                       // [512*16] persistent U slice
    float* hs  = sm + 512 * 16;            // [64*65]  h chunk (padded)
    float* zt  = hs + 64 * 65;             // [64*16]  gate pre-activations
    float* zes = zt + 64 * 16;             // [64*65]  e logits / softmax (padded)

    const int bid = blockIdx.x;
    const int tid = threadIdx.x;
    const bool isE = (bid >= NUBLK);

    // --- load persistent U slice into SMEM (once) ---
    if (!isE) {
        const int u0 = bid * 4;
        const int tc = tid & 15;
        const float* Ug;
        switch (tc >> 2) {
            case 0:  Ug = Ui; break;
            case 1:  Ug = Uf; break;
            case 2:  Ug = Uo; break;
            default: Ug = Uc; break;
        }
        const int lc = u0 + (tc & 3);
        for (int k = tid >> 4; k < Uu; k += NTHR / 16)
            Us[k * 16 + tc] = Ug[(size_t)k * Uu + lc];
    } else {
        const int m0 = (bid - NUBLK) * 4;
        const int tc = tid & 3;
        for (int k = tid >> 2; k < Uu; k += NTHR / 4)
            Us[k * 4 + tc] = Ue[(size_t)k * Mm + m0 + tc];
    }
    __syncthreads();

    const int tx = tid & 7, ty = tid >> 3;        // u-block GEMM map: 8 col-pairs x 16 row-quads
    const int rbase = ty * 4;
    const int etx = tid & 1, ety = tid >> 1;      // e-block GEMM map

    for (int t = 0; t < Tt; t++) {
        const float* hsrc = &g_h2[t & 1][0][0];

        if (!isE) {
            const int u0 = bid * 4;
            // ---- phase 1: z = Z[t] + h @ U_slice ----
            float acc[4][2];
            #pragma unroll
            for (int cc = 0; cc < 2; cc++) {
                int c = tx * 2 + cc;
                int n = (c >> 2) * Uu + u0 + (c & 3);
                float4 z4 = *reinterpret_cast<const float4*>(
                    &g_Z[((size_t)t * NZt + n) * Bb + rbase]);
                acc[0][cc] = z4.x; acc[1][cc] = z4.y;
                acc[2][cc] = z4.z; acc[3][cc] = z4.w;
            }
            for (int kb = 0; kb < 8; kb++) {
                __syncthreads();
                #pragma unroll
                for (int l = 0; l < 32; l++) {
                    int idx = l * NTHR + tid;
                    int r = idx >> 6, kk = idx & 63;
                    hs[r * 65 + kk] = hsrc[r * Uu + kb * 64 + kk];
                }
                __syncthreads();
                #pragma unroll 16
                for (int kk = 0; kk < 64; kk++) {
                    float2 uv = *reinterpret_cast<const float2*>(
                        &Us[(kb * 64 + kk) * 16 + tx * 2]);
                    #pragma unroll
                    for (int i = 0; i < 4; i++) {
                        float hv = hs[(rbase + i) * 65 + kk];
                        acc[i][0] += hv * uv.x;
                        acc[i][1] += hv * uv.y;
                    }
                }
            }
            #pragma unroll
            for (int cc = 0; cc < 2; cc++) {
                int c = tx * 2 + cc;
                #pragma unroll
                for (int i = 0; i < 4; i++) zt[(rbase + i) * 16 + c] = acc[i][cc];
            }

            // ---- wait for e logits (e-blocks finish much earlier) ----
            if (tid == 0) {
                unsigned tgt = (unsigned)(t + 1) * (unsigned)NEBLK;
                while (*(volatile unsigned int*)&g_eflag < tgt) { }
                __threadfence();   // gpu-scope: invalidates L1, acquire
            }
            __syncthreads();

            // ---- softmax over e (redundant per block, cheap) ----
            #pragma unroll
            for (int l = 0; l < 32; l++) {
                int idx = l * NTHR + tid;
                zes[(idx >> 6) * 65 + (idx & 63)] = (&g_ze[0][0])[idx];
            }
            __syncthreads();
            if (tid < 64) {
                float mx = -1e30f;
                #pragma unroll 8
                for (int m = 0; m < 64; m++) mx = fmaxf(mx, zes[tid * 65 + m]);
                float s = 0.0f;
                #pragma unroll 8
                for (int m = 0; m < 64; m++) {
                    float e = __expf(zes[tid * 65 + m] - mx);
                    zes[tid * 65 + m] = e; s += e;
                }
                float inv = 1.0f / s;
                #pragma unroll 8
                for (int m = 0; m < 64; m++) zes[tid * 65 + m] *= inv;
            }
            __syncthreads();

            // ---- phase 2: memory read + cell/hidden update ----
            const int slot = t & 63;
            const int mlim = (t < 64) ? t : 64;
            #pragma unroll
            for (int pp = 0; pp < 2; pp++) {
                int p  = pp * NTHR + tid;
                int b  = p >> 2, uu = p & 3;
                float mc = 0.0f;
                for (int m = 0; m < mlim; m++) {
                    int s2 = (t - 1 - m) & 63;
                    mc += zes[b * 65 + m] * g_cring[s2][b][u0 + uu];
                }
                float iv = zt[b * 16 + uu];
                float fv = zt[b * 16 + 4 + uu];
                float ov = zt[b * 16 + 8 + uu];
                float cv = zt[b * 16 + 12 + uu];
                iv = 1.0f / (1.0f + __expf(-iv));
                fv = 1.0f / (1.0f + __expf(-fv));
                ov = 1.0f / (1.0f + __expf(-ov));
                cv = tanhf(cv);
                float c = fv * mc + iv * cv;
                float h = ov * tanhf(c);
                g_cring[slot][b][u0 + uu] = c;                 // block-private cols: no race
                g_h2[(t + 1) & 1][b][u0 + uu] = h;             // double-buffered
                out[(size_t)b * Tt * Uu + (size_t)t * Uu + u0 + uu] = h;
            }
        } else {
            // ---- e-block: small GEMM producing ze, then flag ----
            const int m0 = (bid - NUBLK) * 4;
            float acc[2];
            #pragma unroll
            for (int cc = 0; cc < 2; cc++)
                acc[cc] = g_Z[((size_t)t * NZt + 4 * Uu + m0 + etx * 2 + cc) * Bb + ety];
            for (int kb = 0; kb < 8; kb++) {
                __syncthreads();
                #pragma unroll
                for (int l = 0; l < 32; l++) {
                    int idx = l * NTHR + tid;
                    int r = idx >> 6, kk = idx & 63;
                    hs[r * 65 + kk] = hsrc[r * Uu + kb * 64 + kk];
                }
                __syncthreads();
                #pragma unroll 16
                for (int kk = 0; kk < 64; kk++) {
                    float2 uv = *reinterpret_cast<const float2*>(
                        &Us[(kb * 64 + kk) * 4 + etx * 2]);
                    float hv = hs[ety * 65 + kk];
                    acc[0] += hv * uv.x;
                    acc[1] += hv * uv.y;
                }
            }
            g_ze[ety][m0 + etx * 2]     = acc[0];
            g_ze[ety][m0 + etx * 2 + 1] = acc[1];
            __threadfence();            // release ze before flagging
            __syncthreads();
            if (tid == 0) atomicAdd(&g_eflag, 1u);
        }

        // ---- grid barrier (striped counters, monotonic targets) ----
        __syncthreads();
        if (tid == 0) { __threadfence(); atomicAdd(&g_bar4[bid & 3], 1u); }
        if (tid < 4) {
            unsigned tgt = (unsigned)(t + 1) * (unsigned)(NBLK / 4);
            while (*(volatile unsigned int*)&g_bar4[tid] < tgt) { }
            __threadfence();            // acquire: invalidate L1 before reading new h
        }
        __syncthreads();
    }
}

// ---------------- launch ----------------
extern "C" void kernel_launch(void* const* d_in, const int* in_sizes, int n_in,
                              void* d_out, int out_size) {
    (void)in_sizes; (void)n_in; (void)out_size;
    const float* x  = (const float*)d_in[0];
    const float* Wi = (const float*)d_in[1];
    const float* Ui = (const float*)d_in[2];
    const float* bi = (const float*)d_in[3];
    const float* Wf = (const float*)d_in[4];
    const float* Uf = (const float*)d_in[5];
    const float* bf = (const float*)d_in[6];
    const float* Wo = (const float*)d_in[7];
    const float* Uo = (const float*)d_in[8];
    const float* bo = (const float*)d_in[9];
    const float* Wc = (const float*)d_in[10];
    const float* Uc = (const float*)d_in[11];
    const float* bc = (const float*)d_in[12];
    const float* We = (const float*)d_in[13];
    const float* Ue = (const float*)d_in[14];
    const float* be = (const float*)d_in[15];
    float* out = (float*)d_out;

    const size_t SMEM = (size_t)(512 * 16 + 64 * 65 + 64 * 16 + 64 * 65) * sizeof(float); // 70144B
    cudaFuncSetAttribute(recur_kernel, cudaFuncAttributeMaxDynamicSharedMemorySize, (int)SMEM);

    init_kernel<<<32, 256>>>();
    dim3 pg(33, Tt);
    precompute_kernel<<<pg, 256>>>(x, Wi, Wf, Wo, Wc, We, bi, bf, bo, bc, be);
    recur_kernel<<<NBLK, NTHR, SMEM>>>(out, Ui, Uf, Uo, Uc, Ue);
}